// round 7
// baseline (speedup 1.0000x reference)
#include <cuda_runtime.h>

// SSIM loss, fused streaming kernel — (s,d) transform + 2 output columns per
// thread. Taps for the column pair come from 6 aligned LDS.128; squares are
// shared between the two columns. sm_103a packed f32x2 math.
// 16x3x512x512 fp32 pred/target -> scalar 1 - mean(ssim_map).

#define IMG   512
#define PLANES 48
#define KW    11
#define KR    5
#define TW    128                // tile width; 64 threads x 2 cols
#define TH    64
#define NRB   7                  // 7*11 = 77 rows streamed >= TH+10
#define SW    (TW + 2*KR)        // 138 staged (s,d) pairs
#define NTHREADS 64
#define GRIDX (IMG/TW)           // 4
#define GRIDY (IMG/TH)           // 8
#define NBLK  (GRIDX*GRIDY*PLANES)  // 1536
#define NPIXD ((double)PLANES * IMG * IMG)

typedef unsigned long long u64;

__device__ double       g_sum;
__device__ unsigned int g_cnt;

__device__ __forceinline__ u64 pk2(float x, float y) {
    u64 r; asm("mov.b64 %0, {%1, %2};" : "=l"(r) : "f"(x), "f"(y)); return r;
}
__device__ __forceinline__ void upk2(u64 v, float& x, float& y) {
    asm("mov.b64 {%0, %1}, %2;" : "=f"(x), "=f"(y) : "l"(v));
}
__device__ __forceinline__ u64 fma2(u64 a, u64 b, u64 c) {
    u64 d; asm("fma.rn.f32x2 %0, %1, %2, %3;" : "=l"(d) : "l"(a), "l"(b), "l"(c));
    return d;
}
__device__ __forceinline__ u64 mul2(u64 a, u64 b) {
    u64 d; asm("mul.rn.f32x2 %0, %1, %2;" : "=l"(d) : "l"(a), "l"(b));
    return d;
}

__global__ __launch_bounds__(NTHREADS, 7)
void ssim_kernel(const float* __restrict__ pred,
                 const float* __restrict__ targ,
                 float* __restrict__ out)
{
    constexpr float W[KW] = {
        0.00102838f, 0.00759876f, 0.03600077f, 0.10936069f, 0.21300554f,
        0.26601173f,
        0.21300554f, 0.10936069f, 0.03600077f, 0.00759876f, 0.00102838f
    };
    constexpr float C1 = 0.0001f;
    constexpr float C2 = 0.0009f;

    __shared__ __align__(16) float2 stg[2][SW];  // interleaved (s,d) rows
    __shared__ float wsum[2];

    const int t  = threadIdx.x;
    const int x0 = blockIdx.x * TW;
    const int y0 = blockIdx.y * TH;
    const float* __restrict__ xin = pred + (size_t)blockIdx.z * IMG * IMG;
    const float* __restrict__ yin = targ + (size_t)blockIdx.z * IMG * IMG;

    // staging columns handled by this thread: t, t+64, t+128 (t<10)
    const int  gxa  = x0 - KR + t;
    const int  gxb  = gxa + 64;          // always in [59, 506] -> in-bounds
    const int  gxc  = gxa + 128;
    const bool tail = (t < SW - 2 * NTHREADS);   // t < 10

    auto ldrow = [&](int j, float& sA, float& dA, float& sB, float& dB,
                     float& sC, float& dC) {
        const int  gy  = y0 - KR + j;
        const bool rok = (gy >= 0) && (gy < IMG);
        const bool okA = rok && (gxa >= 0);
        const bool okC = rok && tail && (gxc < IMG);
        const long b = (long)gy * IMG;
        const float xa = okA ? xin[b + gxa] : 0.0f;
        const float ya = okA ? yin[b + gxa] : 0.0f;
        const float xb = rok ? xin[b + gxb] : 0.0f;
        const float yb = rok ? yin[b + gxb] : 0.0f;
        const float xc = okC ? xin[b + gxc] : 0.0f;
        const float yc = okC ? yin[b + gxc] : 0.0f;
        sA = xa + ya;  dA = xa - ya;
        sB = xb + yb;  dB = xb - yb;
        sC = xc + yc;  dC = xc - yc;
    };
    auto strow = [&](int buf, float sA, float dA, float sB, float dB,
                     float sC, float dC) {
        stg[buf][t]       = make_float2(sA, dA);
        stg[buf][64 + t]  = make_float2(sB, dB);
        if (tail) stg[buf][128 + t] = make_float2(sC, dC);
    };

    // 6 distinct packed weights (Gaussian symmetry)
    u64 WW[6];
    #pragma unroll
    for (int k = 0; k < 6; ++k) WW[k] = pk2(W[k], W[k]);
    const u64 NEG1 = pk2(-1.0f, -1.0f);
    const u64 Z64  = 0ull;

    // per-column ring accumulators, packed (mu_s,mu_d), (E[s^2],E[d^2])
    u64 aMU0[11], aSQ0[11], aMU1[11], aSQ1[11];
    #pragma unroll
    for (int s = 0; s < 11; ++s) {
        aMU0[s] = Z64; aSQ0[s] = Z64; aMU1[s] = Z64; aSQ1[s] = Z64;
    }

    float tsum = 0.0f;

    // preload + stage row 0
    {
        float sA, dA, sB, dB, sC, dC;
        ldrow(0, sA, dA, sB, dB, sC, dC);
        strow(0, sA, dA, sB, dB, sC, dC);
    }
    __syncthreads();

    for (int jb = 0; jb < NRB; ++jb) {
        #pragma unroll
        for (int u = 0; u < 11; ++u) {
            const int j = jb * 11 + u;

            // prefetch next row (overlaps compute)
            float nsA, ndA, nsB, ndB, nsC, ndC;
            ldrow(j + 1, nsA, ndA, nsB, ndB, nsC, ndC);

            // ---- horizontal blur for cols c0=2t, c1=2t+1 ----
            // staged indices 2t .. 2t+11 via 6 aligned LDS.128
            const float4* sp = (const float4*)(&stg[j & 1][2 * t]);
            u64 hmu0 = Z64, hsq0 = Z64, hmu1 = Z64, hsq1 = Z64;
            #pragma unroll
            for (int m = 0; m < 6; ++m) {
                const float4 f = sp[m];
                const u64 v0 = pk2(f.x, f.y);          // position i = 2m
                const u64 v1 = pk2(f.z, f.w);          // position i = 2m+1
                const u64 q0 = mul2(v0, v0);           // shared squares
                const u64 q1 = mul2(v1, v1);
                {   // i=2m: c0 weight W[2m]
                    const int wi = (2*m < 6) ? 2*m : 10 - 2*m;
                    hmu0 = fma2(WW[wi], v0, hmu0);
                    hsq0 = fma2(WW[wi], q0, hsq0);
                }
                if (m >= 1) {   // i=2m: c1 weight W[2m-1]
                    const int wi = (2*m-1 < 6) ? 2*m-1 : 11 - 2*m;
                    hmu1 = fma2(WW[wi], v0, hmu1);
                    hsq1 = fma2(WW[wi], q0, hsq1);
                }
                if (m <= 4) {   // i=2m+1: c0 weight W[2m+1]
                    const int wi = (2*m+1 < 6) ? 2*m+1 : 9 - 2*m;
                    hmu0 = fma2(WW[wi], v1, hmu0);
                    hsq0 = fma2(WW[wi], q1, hsq0);
                }
                {   // i=2m+1: c1 weight W[2m]
                    const int wi = (2*m < 6) ? 2*m : 10 - 2*m;
                    hmu1 = fma2(WW[wi], v1, hmu1);
                    hsq1 = fma2(WW[wi], q1, hsq1);
                }
            }

            // ---- vertical ring update (literal slots) ----
            #pragma unroll
            for (int p = 0; p < KW; ++p) {
                const int ss = (u - p + 11) % 11;
                const int pw = (p < 6) ? p : 10 - p;
                aMU0[ss] = fma2(WW[pw], hmu0, aMU0[ss]);
                aSQ0[ss] = fma2(WW[pw], hsq0, aSQ0[ss]);
                aMU1[ss] = fma2(WW[pw], hmu1, aMU1[ss]);
                aSQ1[ss] = fma2(WW[pw], hsq1, aSQ1[ss]);
            }

            // ---- finalize output row o = j-10 for both columns ----
            {
                const int so = (u + 1) % 11;
                const int o  = j - (KW - 1);
                if (o >= 0 && o < TH) {
                    {
                        const u64 mu2 = mul2(aMU0[so], aMU0[so]);
                        const u64 sg  = fma2(mu2, NEG1, aSQ0[so]);
                        float g0, g1, v0, v1;
                        upk2(mu2, g0, g1);
                        upk2(sg,  v0, v1);
                        const float num = (0.5f*(g0-g1) + C1) * (0.5f*(v0-v1) + C2);
                        const float den = (0.5f*(g0+g1) + C1) * (0.5f*(v0+v1) + C2);
                        tsum += __fdividef(num, den);
                    }
                    {
                        const u64 mu2 = mul2(aMU1[so], aMU1[so]);
                        const u64 sg  = fma2(mu2, NEG1, aSQ1[so]);
                        float g0, g1, v0, v1;
                        upk2(mu2, g0, g1);
                        upk2(sg,  v0, v1);
                        const float num = (0.5f*(g0-g1) + C1) * (0.5f*(v0-v1) + C2);
                        const float den = (0.5f*(g0+g1) + C1) * (0.5f*(v0+v1) + C2);
                        tsum += __fdividef(num, den);
                    }
                }
                aMU0[so] = Z64; aSQ0[so] = Z64;
                aMU1[so] = Z64; aSQ1[so] = Z64;
            }

            // stage prefetched row j+1 (other buffer; overwrites data last
            // read in iter j-1, fenced by that iteration's barrier)
            strow((j + 1) & 1, nsA, ndA, nsB, ndB, nsC, ndC);
            __syncthreads();
        }
    }

    // ---- reduction: warp -> block -> global ----
    #pragma unroll
    for (int off = 16; off > 0; off >>= 1)
        tsum += __shfl_down_sync(0xffffffffu, tsum, off);
    if ((t & 31) == 0) wsum[t >> 5] = tsum;
    __syncthreads();

    if (t == 0) {
        const double bs = (double)wsum[0] + (double)wsum[1];
        atomicAdd(&g_sum, bs);
        __threadfence();
        const unsigned r = atomicAdd(&g_cnt, 1u);
        if (r == NBLK - 1u) {
            const double sall = g_sum;
            out[0] = (float)(1.0 - sall / NPIXD);
            g_sum = 0.0;
            __threadfence();
            g_cnt = 0u;
        }
    }
}

extern "C" void kernel_launch(void* const* d_in, const int* in_sizes, int n_in,
                              void* d_out, int out_size)
{
    const float* pred = (const float*)d_in[0];
    const float* targ = (const float*)d_in[1];
    float* out = (float*)d_out;

    dim3 grid(GRIDX, GRIDY, PLANES);   // 4 x 8 x 48 = 1536 blocks
    ssim_kernel<<<grid, NTHREADS>>>(pred, targ, out);
}

// round 8
// speedup vs baseline: 1.5193x; 1.5193x over previous
#include <cuda_runtime.h>

// SSIM loss, fused streaming kernel — (s,d) transform, two packed f32x2
// rings, 11-row double-buffered staging ring: ONE barrier per 11 rows,
// all buffer offsets literal. sm_103a packed math.
// 16x3x512x512 fp32 pred/target -> scalar 1 - mean(ssim_map).

#define IMG   512
#define PLANES 48
#define KW    11
#define KR    5
#define TW    128
#define TH    64
#define NRB   7                  // 7*11 = 77 rows streamed >= TH+10
#define SW    (TW + 2*KR)        // 138
#define NTHREADS 128
#define GRIDX (IMG/TW)           // 4
#define GRIDY (IMG/TH)           // 8
#define NBLK  (GRIDX*GRIDY*PLANES)  // 1536
#define NPIXD ((double)PLANES * IMG * IMG)

typedef unsigned long long u64;

__device__ double       g_sum;
__device__ unsigned int g_cnt;

__device__ __forceinline__ u64 pk2(float x, float y) {
    u64 r; asm("mov.b64 %0, {%1, %2};" : "=l"(r) : "f"(x), "f"(y)); return r;
}
__device__ __forceinline__ void upk2(u64 v, float& x, float& y) {
    asm("mov.b64 {%0, %1}, %2;" : "=f"(x), "=f"(y) : "l"(v));
}
__device__ __forceinline__ u64 fma2(u64 a, u64 b, u64 c) {
    u64 d; asm("fma.rn.f32x2 %0, %1, %2, %3;" : "=l"(d) : "l"(a), "l"(b), "l"(c));
    return d;
}
__device__ __forceinline__ u64 mul2(u64 a, u64 b) {
    u64 d; asm("mul.rn.f32x2 %0, %1, %2;" : "=l"(d) : "l"(a), "l"(b));
    return d;
}

__global__ __launch_bounds__(NTHREADS, 5)
void ssim_kernel(const float* __restrict__ pred,
                 const float* __restrict__ targ,
                 float* __restrict__ out)
{
    constexpr float W[KW] = {
        0.00102838f, 0.00759876f, 0.03600077f, 0.10936069f, 0.21300554f,
        0.26601173f,
        0.21300554f, 0.10936069f, 0.03600077f, 0.00759876f, 0.00102838f
    };
    constexpr float C1 = 0.0001f;
    constexpr float C2 = 0.0009f;

    // 2 x 11-row staging ring of interleaved (s,d) rows: 24.3 KB
    __shared__ float2 stg[2][KW][SW];
    __shared__ float  wsum[4];

    const int t  = threadIdx.x;
    const int x0 = blockIdx.x * TW;
    const int y0 = blockIdx.y * TH;
    const float* __restrict__ xin = pred + (size_t)blockIdx.z * IMG * IMG;
    const float* __restrict__ yin = targ + (size_t)blockIdx.z * IMG * IMG;

    const int  gx0  = x0 - KR + t;
    const int  gx1  = gx0 + TW;
    const bool tail = (t < SW - TW);

    // load one padded row; return (s,d) = (x+y, x-y) pairs
    auto ldrow = [&](int j, float& s0, float& d0, float& s1, float& d1) {
        const int  gy  = y0 - KR + j;
        const bool rok = (gy >= 0) && (gy < IMG);
        const bool ok0 = rok && (gx0 >= 0) && (gx0 < IMG);
        const bool ok1 = rok && tail && (gx1 < IMG);
        const long b = (long)gy * IMG;
        const float ax0 = ok0 ? xin[b + gx0] : 0.0f;
        const float ay0 = ok0 ? yin[b + gx0] : 0.0f;
        const float ax1 = ok1 ? xin[b + gx1] : 0.0f;
        const float ay1 = ok1 ? yin[b + gx1] : 0.0f;
        s0 = ax0 + ay0;  d0 = ax0 - ay0;
        s1 = ax1 + ay1;  d1 = ax1 - ay1;
    };

    // 6 distinct packed weights (Gaussian symmetry)
    u64 WW[6];
    #pragma unroll
    for (int k = 0; k < 6; ++k) WW[k] = pk2(W[k], W[k]);
    const u64 NEG1 = pk2(-1.0f, -1.0f);
    const u64 Z64  = 0ull;

    // ring accumulators: packed (mu_s, mu_d) and (E[s^2], E[d^2])
    u64 aMU[11], aSQ[11];
    #pragma unroll
    for (int s = 0; s < 11; ++s) { aMU[s] = Z64; aSQ[s] = Z64; }

    float tsum = 0.0f;

    // ---- prologue: stage rows 0..10 into ring half 0 ----
    #pragma unroll
    for (int r = 0; r < KW; ++r) {
        float s0, d0, s1, d1;
        ldrow(r, s0, d0, s1, d1);
        stg[0][r][t] = make_float2(s0, d0);
        if (tail) stg[0][r][TW + t] = make_float2(s1, d1);
    }
    __syncthreads();

    for (int jb = 0; jb < NRB; ++jb) {
        const float2 (*cur)[SW] = stg[jb & 1];        // uniform per block
        float2 (*nxt)[SW]       = stg[(jb + 1) & 1];

        #pragma unroll
        for (int u = 0; u < 11; ++u) {
            const int j = jb * 11 + u;

            // prefetch row j+11 (consumed next block, after the barrier)
            float ns0, nd0, ns1, nd1;
            ldrow(j + 11, ns0, nd0, ns1, nd1);

            // ---- horizontal blur from cur[u] (literal offset) ----
            const u64* s = (const u64*)cur[u];
            u64 hmu = Z64, hsq = Z64;
            #pragma unroll
            for (int k = 0; k < KW; ++k) {
                const int kw = (k < 6) ? k : 10 - k;    // literal
                const u64 p  = s[t + k];                // (s, d) LDS.64
                const u64 pp = mul2(p, p);              // (s^2, d^2)
                hmu = fma2(WW[kw], p,  hmu);
                hsq = fma2(WW[kw], pp, hsq);
            }

            // stage prefetched row into nxt[u] (literal offset). Other ring
            // half: no reader this block; visible next block via the barrier.
            nxt[u][t] = make_float2(ns0, nd0);
            if (tail) nxt[u][TW + t] = make_float2(ns1, nd1);

            // ---- vertical ring update (literal slots) ----
            #pragma unroll
            for (int p = 0; p < KW; ++p) {
                const int ss = (u - p + 11) % 11;       // literal
                const int pw = (p < 6) ? p : 10 - p;    // literal
                aMU[ss] = fma2(WW[pw], hmu, aMU[ss]);
                aSQ[ss] = fma2(WW[pw], hsq, aSQ[ss]);
            }

            // ---- finalize output row o = j-10, reset slot ----
            {
                const int so = (u + 1) % 11;
                const int o  = j - (KW - 1);
                if (o >= 0 && o < TH) {
                    const u64 mu  = aMU[so];
                    const u64 mu2 = mul2(mu, mu);             // (mus^2, mud^2)
                    const u64 sg  = fma2(mu2, NEG1, aSQ[so]); // (sig_s, sig_d)
                    float g0, g1, v0, v1;
                    upk2(mu2, g0, g1);
                    upk2(sg,  v0, v1);
                    // 2*mu_xy=(g0-g1)/2; mu_x^2+mu_y^2=(g0+g1)/2
                    // 2*sg_xy=(v0-v1)/2; sg_x+sg_y    =(v0+v1)/2
                    const float num = (0.5f*(g0 - g1) + C1) * (0.5f*(v0 - v1) + C2);
                    const float den = (0.5f*(g0 + g1) + C1) * (0.5f*(v0 + v1) + C2);
                    tsum += __fdividef(num, den);
                }
                aMU[so] = Z64; aSQ[so] = Z64;
            }
        }
        // one barrier per 11 rows: publishes nxt[*], retires cur[*]
        __syncthreads();
    }

    // ---- reduction: warp -> block -> global ----
    #pragma unroll
    for (int off = 16; off > 0; off >>= 1)
        tsum += __shfl_down_sync(0xffffffffu, tsum, off);
    if ((t & 31) == 0) wsum[t >> 5] = tsum;
    __syncthreads();

    if (t == 0) {
        const double bs = (double)wsum[0] + (double)wsum[1]
                        + (double)wsum[2] + (double)wsum[3];
        atomicAdd(&g_sum, bs);
        __threadfence();
        const unsigned r = atomicAdd(&g_cnt, 1u);
        if (r == NBLK - 1u) {
            const double sall = g_sum;
            out[0] = (float)(1.0 - sall / NPIXD);
            g_sum = 0.0;
            __threadfence();
            g_cnt = 0u;
        }
    }
}

extern "C" void kernel_launch(void* const* d_in, const int* in_sizes, int n_in,
                              void* d_out, int out_size)
{
    const float* pred = (const float*)d_in[0];
    const float* targ = (const float*)d_in[1];
    float* out = (float*)d_out;

    dim3 grid(GRIDX, GRIDY, PLANES);   // 4 x 8 x 48 = 1536 blocks
    ssim_kernel<<<grid, NTHREADS>>>(pred, targ, out);
}